// round 14
// baseline (speedup 1.0000x reference)
#include <cuda_runtime.h>
#include <cuda_fp16.h>
#include <cstdint>

// Sliding-window attention B=2 H=12 T=4096 D=64 fp32, window [q-128, q+127].
// fp16 m16n8k16 mma.sync; ldmatrix K/V frags; P stays in registers.
// Round 14: single-span smem (one barrier) + BRANCHLESS fully-unrolled
// 17-pair mainloop (every warp runs pairs gp=w..w+16; edge masking is
// compile-time at j=0/16) so ptxas can schedule across pair boundaries.
// Boundary CTAs (q0==0 / q0==T-128; 2 of 32) take a cold dynamic path.

constexpr int T_FIX = 4096;
constexpr int MQ    = 128;
constexpr int STR   = 36;              // row stride in u32 units; conflict-free
constexpr int KVF   = 384 * STR;       // one tensor: 13824 u32 = 55296 B
constexpr int SM_BYTES = 2 * KVF * 4;  // 110592 B

__device__ __forceinline__ uint32_t smem_u32(const void* p) {
    uint32_t a;
    asm("{ .reg .u64 t; cvta.to.shared.u64 t, %1; cvt.u32.u64 %0, t; }" : "=r"(a) : "l"(p));
    return a;
}
__device__ __forceinline__ float ex2(float x) {
    float y; asm("ex2.approx.ftz.f32 %0, %1;" : "=f"(y) : "f"(x)); return y;
}
__device__ __forceinline__ uint32_t packh2(float lo, float hi) {
    __half2 h = __floats2half2_rn(lo, hi);
    return *(uint32_t*)&h;
}
__device__ __forceinline__ void mma16(float* c, const uint32_t* a,
                                      uint32_t b0, uint32_t b1) {
    asm volatile(
        "mma.sync.aligned.m16n8k16.row.col.f32.f16.f16.f32 "
        "{%0,%1,%2,%3}, {%4,%5,%6,%7}, {%8,%9}, {%0,%1,%2,%3};"
        : "+f"(c[0]), "+f"(c[1]), "+f"(c[2]), "+f"(c[3])
        : "r"(a[0]), "r"(a[1]), "r"(a[2]), "r"(a[3]), "r"(b0), "r"(b1));
}
#define LDSM4(r0,r1,r2,r3,addr) \
    asm volatile("ldmatrix.sync.aligned.m8n8.x4.shared.b16 {%0,%1,%2,%3}, [%4];" \
        : "=r"(r0),"=r"(r1),"=r"(r2),"=r"(r3) : "r"(addr))
#define LDSM4T(r0,r1,r2,r3,addr) \
    asm volatile("ldmatrix.sync.aligned.m8n8.x4.trans.shared.b16 {%0,%1,%2,%3}, [%4];" \
        : "=r"(r0),"=r"(r1),"=r"(r2),"=r"(r3) : "r"(addr))

__global__ __launch_bounds__(256, 2)
void swa_f16_kernel(const float* __restrict__ Q, const float* __restrict__ K,
                    const float* __restrict__ V, float* __restrict__ O)
{
    extern __shared__ uint32_t smem[];   // [ K(384xSTR) | V(384xSTR) ]
    uint32_t* sK = smem;
    uint32_t* sV = smem + KVF;

    const int tid  = threadIdx.x;
    const int lane = tid & 31;
    const int w    = tid >> 5;

    const int ntiles = T_FIX / MQ;                  // 32
    const int bh = blockIdx.x / ntiles;
    const int q0 = (blockIdx.x % ntiles) * MQ;
    const size_t base = (size_t)bh * T_FIX * 64;
    const float*  Qb = Q + base;
    const float4* Kg = (const float4*)(K + base);
    const float4* Vg = (const float4*)(V + base);
    float*        Ob = O + base;

    const float SC = 1.4426950408889634f * 0.125f;  // log2(e)/sqrt(64)

    const int rA = w * 16 + (lane >> 2);
    const int cA = lane & 3;

    // ---- Q a-fragments straight from gmem (prologue-only LDG.64s) ----
    uint32_t qa[4][4];
    {
        const float* q0p = Qb + (size_t)(q0 + rA) * 64;
        const float* q1p = Qb + (size_t)(q0 + rA + 8) * 64;
        #pragma unroll
        for (int s = 0; s < 4; s++) {
            float2 a0 = *(const float2*)(q0p + s * 16 + 2 * cA);
            float2 a1 = *(const float2*)(q1p + s * 16 + 2 * cA);
            float2 a2 = *(const float2*)(q0p + s * 16 + 8 + 2 * cA);
            float2 a3 = *(const float2*)(q1p + s * 16 + 8 + 2 * cA);
            qa[s][0] = packh2(a0.x * SC, a0.y * SC);
            qa[s][1] = packh2(a1.x * SC, a1.y * SC);
            qa[s][2] = packh2(a2.x * SC, a2.y * SC);
            qa[s][3] = packh2(a3.x * SC, a3.y * SC);
        }
    }

    // ---- Fill the whole 384-key span (keys q0-128 .. q0+255), f16 ----
    {
        const int kbase = q0 - 128;
        #pragma unroll 8
        for (int i = 0; i < 24; i++) {
            int idx = tid + i * 256;                // 6144 float4 per tensor
            int key = idx >> 4, c4 = idx & 15;
            int gk  = kbase + key;
            if ((unsigned)gk < (unsigned)T_FIX) {
                float4 kv = Kg[(size_t)gk * 16 + c4];
                float4 vv = Vg[(size_t)gk * 16 + c4];
                sK[key * STR + c4 * 2]     = packh2(kv.x, kv.y);
                sK[key * STR + c4 * 2 + 1] = packh2(kv.z, kv.w);
                sV[key * STR + c4 * 2]     = packh2(vv.x, vv.y);
                sV[key * STR + c4 * 2 + 1] = packh2(vv.z, vv.w);
            }
        }
    }
    __syncthreads();   // the ONLY barrier before the epilogue

    // ---- ldmatrix per-lane base addresses (bytes) ----
    const int lr  = lane & 7;
    const int hib = (lane >> 3) & 1;
    const int sec = lane >> 4;
    const uint32_t qk_base = smem_u32(sK) + ((sec * 8 + lr) * STR + hib * 4) * 4;
    const uint32_t pv_base = smem_u32(sV) + ((hib * 8 + lr) * STR + sec * 4) * 4;

    float o[8][4];
    #pragma unroll
    for (int n = 0; n < 8; n++)
        #pragma unroll
        for (int j = 0; j < 4; j++) o[n][j] = 0.f;
    float l0 = 0.f, l1 = 0.f;

    if (q0 != 0 && q0 != T_FIX - MQ) {
        // ================= hot path: 30/32 CTAs =================
        // every warp runs exactly pairs gp = w .. w+16, all in-bounds.
        uint32_t qk_p = qk_base + (w * 16 * STR) * 4;
        uint32_t pv_p = pv_base + (w * 16 * STR) * 4;
        const int cc0 = w * 16 + 2 * cA;            // cc for j=0

        #pragma unroll
        for (int j = 0; j < 17; j++) {
            // -- QK: two 8-key tiles, 4 k-steps of 16 dims --
            float sA[4] = {0.f, 0.f, 0.f, 0.f};
            float sB[4] = {0.f, 0.f, 0.f, 0.f};
            #pragma unroll
            for (int s = 0; s < 4; s++) {
                uint32_t r0, r1, r2, r3;
                LDSM4(r0, r1, r2, r3, qk_p + s * 32);
                mma16(sA, qa[s], r0, r1);
                mma16(sB, qa[s], r2, r3);
            }

            float pA00, pA01, pA10, pA11, pB00, pB01, pB10, pB11;
            if (j != 0 && j != 16) {                // compile-time under unroll
                pA00 = ex2(sA[0]); pA01 = ex2(sA[1]);
                pA10 = ex2(sA[2]); pA11 = ex2(sA[3]);
                pB00 = ex2(sB[0]); pB01 = ex2(sB[1]);
                pB10 = ex2(sB[2]); pB11 = ex2(sB[3]);
            } else {
                const int cc = cc0 + j * 16;
                pA00 = ((unsigned)(cc     - rA)      < 256u) ? ex2(sA[0]) : 0.f;
                pA01 = ((unsigned)(cc + 1 - rA)      < 256u) ? ex2(sA[1]) : 0.f;
                pA10 = ((unsigned)(cc     - rA - 8)  < 256u) ? ex2(sA[2]) : 0.f;
                pA11 = ((unsigned)(cc + 1 - rA - 8)  < 256u) ? ex2(sA[3]) : 0.f;
                pB00 = ((unsigned)(cc + 8 - rA)      < 256u) ? ex2(sB[0]) : 0.f;
                pB01 = ((unsigned)(cc + 9 - rA)      < 256u) ? ex2(sB[1]) : 0.f;
                pB10 = ((unsigned)(cc + 8 - rA - 8)  < 256u) ? ex2(sB[2]) : 0.f;
                pB11 = ((unsigned)(cc + 9 - rA - 8)  < 256u) ? ex2(sB[3]) : 0.f;
            }
            l0 += (pA00 + pA01) + (pB00 + pB01);
            l1 += (pA10 + pA11) + (pB10 + pB11);

            uint32_t pa[4];
            pa[0] = packh2(pA00, pA01);
            pa[1] = packh2(pA10, pA11);
            pa[2] = packh2(pB00, pB01);
            pa[3] = packh2(pB10, pB11);

            #pragma unroll
            for (int ndp = 0; ndp < 4; ndp++) {
                uint32_t v0, v1, v2, v3;
                LDSM4T(v0, v1, v2, v3, pv_p + ndp * 32);
                mma16(o[2 * ndp],     pa, v0, v1);
                mma16(o[2 * ndp + 1], pa, v2, v3);
            }

            qk_p += 16 * STR * 4;
            pv_p += 16 * STR * 4;
        }
    } else {
        // ================= cold path: boundary CTAs (2/32) =================
        const int glo = (q0 == 0) ? 8 : 0;
        const int ghi = (q0 == T_FIX - MQ) ? 15 : 23;
        const int lo  = (w > glo) ? w : glo;
        const int hi  = (w + 16 < ghi) ? (w + 16) : ghi;

        for (int gp = lo; gp <= hi; gp++) {
            float sA[4] = {0.f, 0.f, 0.f, 0.f};
            float sB[4] = {0.f, 0.f, 0.f, 0.f};
            const uint32_t qk_p = qk_base + (gp * 16 * STR) * 4;
            #pragma unroll
            for (int s = 0; s < 4; s++) {
                uint32_t r0, r1, r2, r3;
                LDSM4(r0, r1, r2, r3, qk_p + s * 32);
                mma16(sA, qa[s], r0, r1);
                mma16(sB, qa[s], r2, r3);
            }

            const int cc = gp * 16 + 2 * cA;
            float pA00 = ((unsigned)(cc     - rA)      < 256u) ? ex2(sA[0]) : 0.f;
            float pA01 = ((unsigned)(cc + 1 - rA)      < 256u) ? ex2(sA[1]) : 0.f;
            float pA10 = ((unsigned)(cc     - rA - 8)  < 256u) ? ex2(sA[2]) : 0.f;
            float pA11 = ((unsigned)(cc + 1 - rA - 8)  < 256u) ? ex2(sA[3]) : 0.f;
            float pB00 = ((unsigned)(cc + 8 - rA)      < 256u) ? ex2(sB[0]) : 0.f;
            float pB01 = ((unsigned)(cc + 9 - rA)      < 256u) ? ex2(sB[1]) : 0.f;
            float pB10 = ((unsigned)(cc + 8 - rA - 8)  < 256u) ? ex2(sB[2]) : 0.f;
            float pB11 = ((unsigned)(cc + 9 - rA - 8)  < 256u) ? ex2(sB[3]) : 0.f;
            l0 += (pA00 + pA01) + (pB00 + pB01);
            l1 += (pA10 + pA11) + (pB10 + pB11);

            uint32_t pa[4];
            pa[0] = packh2(pA00, pA01);
            pa[1] = packh2(pA10, pA11);
            pa[2] = packh2(pB00, pB01);
            pa[3] = packh2(pB10, pB11);

            const uint32_t pv_p = pv_base + (gp * 16 * STR) * 4;
            #pragma unroll
            for (int ndp = 0; ndp < 4; ndp++) {
                uint32_t v0, v1, v2, v3;
                LDSM4T(v0, v1, v2, v3, pv_p + ndp * 32);
                mma16(o[2 * ndp],     pa, v0, v1);
                mma16(o[2 * ndp + 1], pa, v2, v3);
            }
        }
    }

    // ---- normalize rows and store ----
    l0 += __shfl_xor_sync(0xffffffffu, l0, 1);
    l0 += __shfl_xor_sync(0xffffffffu, l0, 2);
    l1 += __shfl_xor_sync(0xffffffffu, l1, 1);
    l1 += __shfl_xor_sync(0xffffffffu, l1, 2);
    const float inv0 = __frcp_rn(l0);
    const float inv1 = __frcp_rn(l1);

    float* orow0 = Ob + (size_t)(q0 + rA) * 64;
    float* orow1 = Ob + (size_t)(q0 + rA + 8) * 64;
    #pragma unroll
    for (int nd = 0; nd < 8; nd++) {
        float2 u0 = make_float2(o[nd][0] * inv0, o[nd][1] * inv0);
        float2 u1 = make_float2(o[nd][2] * inv1, o[nd][3] * inv1);
        *(float2*)(orow0 + nd * 8 + 2 * cA) = u0;
        *(float2*)(orow1 + nd * 8 + 2 * cA) = u1;
    }
}

extern "C" void kernel_launch(void* const* d_in, const int* in_sizes, int n_in,
                              void* d_out, int out_size) {
    const float* Q = (const float*)d_in[0];
    const float* K = (const float*)d_in[1];
    const float* V = (const float*)d_in[2];
    float*       O = (float*)d_out;

    const int BH = in_sizes[0] / (T_FIX * 64);      // 24
    static bool attr_set = false;
    if (!attr_set) {
        cudaFuncSetAttribute(swa_f16_kernel,
                             cudaFuncAttributeMaxDynamicSharedMemorySize, SM_BYTES);
        attr_set = true;
    }
    dim3 grid(BH * (T_FIX / MQ));                   // 768
    swa_f16_kernel<<<grid, 256, SM_BYTES>>>(Q, K, V, O);
}

// round 15
// speedup vs baseline: 1.0625x; 1.0625x over previous
#include <cuda_runtime.h>
#include <cuda_fp16.h>
#include <cstdint>

// Sliding-window attention B=2 H=12 T=4096 D=64 fp32, window [q-128, q+127].
// fp16 m16n8k16 mma.sync; ldmatrix K/V frags; P stays in registers.
// Round 15 = round 12 (best: double-buffered K/V stages, chunk-level OOB
// skip) + SPLIT QK accumulator chains: each score tile accumulates in two
// independent 2-deep HMMA chains (merged by FADDs) instead of one 4-deep
// chain, halving the serial-latency component of every pair.

constexpr int T_FIX = 4096;
constexpr int MQ    = 128;
constexpr int STR   = 36;            // row stride in u32 units; conflict-free
constexpr int QF    = 128 * STR;     // Q staging: 4608 u32
constexpr int KVF   = 64 * STR;      // one tensor per stage: 2304 u32
constexpr int STAGE = 2 * KVF;       // K+V per stage: 4608 u32
constexpr int SM_BYTES = (QF + 2 * STAGE) * 4;   // 55296 B

__device__ __forceinline__ uint32_t smem_u32(const void* p) {
    uint32_t a;
    asm("{ .reg .u64 t; cvta.to.shared.u64 t, %1; cvt.u32.u64 %0, t; }" : "=r"(a) : "l"(p));
    return a;
}
__device__ __forceinline__ float ex2(float x) {
    float y; asm("ex2.approx.ftz.f32 %0, %1;" : "=f"(y) : "f"(x)); return y;
}
__device__ __forceinline__ uint32_t packh2(float lo, float hi) {
    __half2 h = __floats2half2_rn(lo, hi);
    return *(uint32_t*)&h;
}
__device__ __forceinline__ void mma16(float* c, const uint32_t* a,
                                      uint32_t b0, uint32_t b1) {
    asm volatile(
        "mma.sync.aligned.m16n8k16.row.col.f32.f16.f16.f32 "
        "{%0,%1,%2,%3}, {%4,%5,%6,%7}, {%8,%9}, {%0,%1,%2,%3};"
        : "+f"(c[0]), "+f"(c[1]), "+f"(c[2]), "+f"(c[3])
        : "r"(a[0]), "r"(a[1]), "r"(a[2]), "r"(a[3]), "r"(b0), "r"(b1));
}
#define LDSM4(r0,r1,r2,r3,addr) \
    asm volatile("ldmatrix.sync.aligned.m8n8.x4.shared.b16 {%0,%1,%2,%3}, [%4];" \
        : "=r"(r0),"=r"(r1),"=r"(r2),"=r"(r3) : "r"(addr))
#define LDSM4T(r0,r1,r2,r3,addr) \
    asm volatile("ldmatrix.sync.aligned.m8n8.x4.trans.shared.b16 {%0,%1,%2,%3}, [%4];" \
        : "=r"(r0),"=r"(r1),"=r"(r2),"=r"(r3) : "r"(addr))

__global__ __launch_bounds__(256, 2)
void swa_f16_kernel(const float* __restrict__ Q, const float* __restrict__ K,
                    const float* __restrict__ V, float* __restrict__ O)
{
    extern __shared__ uint32_t smem[];   // [Q | stage0 K,V | stage1 K,V]

    const int tid  = threadIdx.x;
    const int lane = tid & 31;
    const int w    = tid >> 5;

    const int ntiles = T_FIX / MQ;                  // 32
    const int bh = blockIdx.x / ntiles;
    const int q0 = (blockIdx.x % ntiles) * MQ;
    const size_t base = (size_t)bh * T_FIX * 64;
    const float4* Qg = (const float4*)(Q + base);
    const float4* Kg = (const float4*)(K + base);
    const float4* Vg = (const float4*)(V + base);
    float*        Ob = O + base;

    const float SC = 1.4426950408889634f * 0.125f;  // log2(e)/sqrt(64)

    // chunk c covers keys [q0-128+64c, q0-64+64c); 64-aligned -> all-in or all-out
    auto chunk_ok = [&](int c) {
        int kb = q0 - 128 + c * 64;
        return (unsigned)kb < (unsigned)T_FIX;
    };
    // fill stage (c&1) with chunk c's K/V (f16); chunk guaranteed in-bounds
    auto fill = [&](int c) {
        const int kbase = q0 - 128 + c * 64;
        uint32_t* kbuf = smem + QF + (c & 1) * STAGE;
        uint32_t* vbuf = kbuf + KVF;
        #pragma unroll
        for (int i = 0; i < 4; i++) {
            int idx = tid + i * 256;
            int key = idx >> 4, c4 = idx & 15;
            int gk  = kbase + key;
            float4 kv = Kg[(size_t)gk * 16 + c4];
            float4 vv = Vg[(size_t)gk * 16 + c4];
            kbuf[key * STR + c4 * 2]     = packh2(kv.x, kv.y);
            kbuf[key * STR + c4 * 2 + 1] = packh2(kv.z, kv.w);
            vbuf[key * STR + c4 * 2]     = packh2(vv.x, vv.y);
            vbuf[key * STR + c4 * 2 + 1] = packh2(vv.z, vv.w);
        }
    };

    // ---- Prologue: stage Q (scaled, f16) + fill chunk 0 ----
    #pragma unroll
    for (int i = 0; i < 8; i++) {
        int idx = tid + i * 256;
        int row = idx >> 4, c4 = idx & 15;
        float4 v = Qg[(size_t)(q0 + row) * 16 + c4];
        smem[row * STR + c4 * 2]     = packh2(v.x * SC, v.y * SC);
        smem[row * STR + c4 * 2 + 1] = packh2(v.z * SC, v.w * SC);
    }
    if (chunk_ok(0)) fill(0);
    __syncthreads();

    // ---- Q a-fragments (m16n8k16): qa[s] covers dims 16s..16s+15 ----
    const int rA = w * 16 + (lane >> 2);
    const int cA = lane & 3;
    uint32_t qa[4][4];
    #pragma unroll
    for (int s = 0; s < 4; s++) {
        qa[s][0] = smem[rA * STR + s * 8 + cA];
        qa[s][1] = smem[(rA + 8) * STR + s * 8 + cA];
        qa[s][2] = smem[rA * STR + s * 8 + 4 + cA];
        qa[s][3] = smem[(rA + 8) * STR + s * 8 + 4 + cA];
    }

    // ---- ldmatrix per-lane offsets (bytes, within a stage) ----
    const int lr  = lane & 7;
    const int hib = (lane >> 3) & 1;
    const int sec = lane >> 4;
    const uint32_t sb = smem_u32(smem);
    const uint32_t qk_lane = ((sec * 8 + lr) * STR + hib * 4) * 4;
    const uint32_t pv_lane = ((hib * 8 + lr) * STR + sec * 4) * 4 + KVF * 4;

    float o[8][4];
    #pragma unroll
    for (int n = 0; n < 8; n++)
        #pragma unroll
        for (int j = 0; j < 4; j++) o[n][j] = 0.f;
    float l0 = 0.f, l1 = 0.f;

    for (int c = 0; c < 6; c++) {
        if (chunk_ok(c)) {
            const uint32_t stb = sb + (QF + (c & 1) * STAGE) * 4;

            // ---- 4 pairs of 16 keys each ----
            #pragma unroll
            for (int st = 0; st < 4; st++) {
                const int gp = c * 4 + st;
                if (gp < w || gp > w + 16) continue;    // warp-uniform band skip

                // -- QK: two 8-key tiles, 4 k-steps in 2 independent chains --
                float sAa[4] = {0.f, 0.f, 0.f, 0.f};
                float sAb[4] = {0.f, 0.f, 0.f, 0.f};
                float sBa[4] = {0.f, 0.f, 0.f, 0.f};
                float sBb[4] = {0.f, 0.f, 0.f, 0.f};
                const uint32_t qk_p = stb + qk_lane + (st * 16 * STR) * 4;
                {
                    uint32_t r0, r1, r2, r3;
                    LDSM4(r0, r1, r2, r3, qk_p);
                    mma16(sAa, qa[0], r0, r1);
                    mma16(sBa, qa[0], r2, r3);
                    LDSM4(r0, r1, r2, r3, qk_p + 32);
                    mma16(sAb, qa[1], r0, r1);
                    mma16(sBb, qa[1], r2, r3);
                    LDSM4(r0, r1, r2, r3, qk_p + 64);
                    mma16(sAa, qa[2], r0, r1);
                    mma16(sBa, qa[2], r2, r3);
                    LDSM4(r0, r1, r2, r3, qk_p + 96);
                    mma16(sAb, qa[3], r0, r1);
                    mma16(sBb, qa[3], r2, r3);
                }
                float sA[4], sB[4];
                #pragma unroll
                for (int j = 0; j < 4; j++) {
                    sA[j] = sAa[j] + sAb[j];
                    sB[j] = sBa[j] + sBb[j];
                }

                // -- softmax: interior fast path; edge pairs window-mask only --
                float pA00, pA01, pA10, pA11, pB00, pB01, pB10, pB11;
                if (gp > w && gp < w + 16) {
                    pA00 = ex2(sA[0]); pA01 = ex2(sA[1]);
                    pA10 = ex2(sA[2]); pA11 = ex2(sA[3]);
                    pB00 = ex2(sB[0]); pB01 = ex2(sB[1]);
                    pB10 = ex2(sB[2]); pB11 = ex2(sB[3]);
                } else {
                    const int cc = c * 64 + st * 16 + 2 * cA;   // local col of sA c0
                    pA00 = ((unsigned)(cc     - rA)      < 256u) ? ex2(sA[0]) : 0.f;
                    pA01 = ((unsigned)(cc + 1 - rA)      < 256u) ? ex2(sA[1]) : 0.f;
                    pA10 = ((unsigned)(cc     - rA - 8)  < 256u) ? ex2(sA[2]) : 0.f;
                    pA11 = ((unsigned)(cc + 1 - rA - 8)  < 256u) ? ex2(sA[3]) : 0.f;
                    pB00 = ((unsigned)(cc + 8 - rA)      < 256u) ? ex2(sB[0]) : 0.f;
                    pB01 = ((unsigned)(cc + 9 - rA)      < 256u) ? ex2(sB[1]) : 0.f;
                    pB10 = ((unsigned)(cc + 8 - rA - 8)  < 256u) ? ex2(sB[2]) : 0.f;
                    pB11 = ((unsigned)(cc + 9 - rA - 8)  < 256u) ? ex2(sB[3]) : 0.f;
                }
                l0 += (pA00 + pA01) + (pB00 + pB01);
                l1 += (pA10 + pA11) + (pB10 + pB11);

                // -- c-frag -> PV a-frag, in registers --
                uint32_t pa[4];
                pa[0] = packh2(pA00, pA01);
                pa[1] = packh2(pA10, pA11);
                pa[2] = packh2(pB00, pB01);
                pa[3] = packh2(pB10, pB11);

                // -- PV: one k16-step over these 16 keys, 8 dim-tiles --
                const uint32_t pv_p = stb + pv_lane + (st * 16 * STR) * 4;
                #pragma unroll
                for (int ndp = 0; ndp < 4; ndp++) {
                    uint32_t v0, v1, v2, v3;
                    LDSM4T(v0, v1, v2, v3, pv_p + ndp * 32);
                    mma16(o[2 * ndp],     pa, v0, v1);
                    mma16(o[2 * ndp + 1], pa, v2, v3);
                }
            }
        }

        // ---- fill next chunk into the other stage (overlaps other warps'
        //      compute; stage of chunk c is reused only after the barrier) ----
        if (c < 5 && chunk_ok(c + 1)) fill(c + 1);
        __syncthreads();
    }

    // ---- normalize rows and store ----
    l0 += __shfl_xor_sync(0xffffffffu, l0, 1);
    l0 += __shfl_xor_sync(0xffffffffu, l0, 2);
    l1 += __shfl_xor_sync(0xffffffffu, l1, 1);
    l1 += __shfl_xor_sync(0xffffffffu, l1, 2);
    const float inv0 = __frcp_rn(l0);
    const float inv1 = __frcp_rn(l1);

    float* orow0 = Ob + (size_t)(q0 + rA) * 64;
    float* orow1 = Ob + (size_t)(q0 + rA + 8) * 64;
    #pragma unroll
    for (int nd = 0; nd < 8; nd++) {
        float2 u0 = make_float2(o[nd][0] * inv0, o[nd][1] * inv0);
        float2 u1 = make_float2(o[nd][2] * inv1, o[nd][3] * inv1);
        *(float2*)(orow0 + nd * 8 + 2 * cA) = u0;
        *(float2*)(orow1 + nd * 8 + 2 * cA) = u1;
    }
}

extern "C" void kernel_launch(void* const* d_in, const int* in_sizes, int n_in,
                              void* d_out, int out_size) {
    const float* Q = (const float*)d_in[0];
    const float* K = (const float*)d_in[1];
    const float* V = (const float*)d_in[2];
    float*       O = (float*)d_out;

    const int BH = in_sizes[0] / (T_FIX * 64);      // 24
    static bool attr_set = false;
    if (!attr_set) {
        cudaFuncSetAttribute(swa_f16_kernel,
                             cudaFuncAttributeMaxDynamicSharedMemorySize, SM_BYTES);
        attr_set = true;
    }
    dim3 grid(BH * (T_FIX / MQ));                   // 768
    swa_f16_kernel<<<grid, 256, SM_BYTES>>>(Q, K, V, O);
}